// round 1
// baseline (speedup 1.0000x reference)
#include <cuda_runtime.h>
#include <cstdint>

#define NPLANES 16384      // 64*256
#define HM 50
#define WM 50
#define HH 56
#define WW 56
#define NTOT 51380224      // 64*256*56*56
#define NVEC (NTOT/4)      // 12845056 float4s
#define ROWWORDS (NPLANES*HH)

// blocked mask: one 64-bit word per output row (56 bits used), per plane
__device__ unsigned long long g_blocked[ROWWORDS];   // 7.34 MB
__device__ unsigned long long g_count;               // total blocked pixels

__global__ void init_kernel() { g_count = 0ULL; }

// One warp per (b,c) plane: threshold mask_u, bitpack rows, dilate 7x7, count.
__global__ __launch_bounds__(256) void mask_kernel(const float* __restrict__ mask_u) {
    // gamma exactly as Python float64 arithmetic, then cast to f32 (JAX weak-type)
    const float gamma = (float)(0.1 / 49.0 * 3136.0 / 2500.0);

    __shared__ unsigned long long rows[8][HM];
    const int warp  = threadIdx.x >> 5;
    const int lane  = threadIdx.x & 31;
    const int plane = blockIdx.x * 8 + warp;

    const float* base = mask_u + (size_t)plane * (HM * WM);

    for (int r = 0; r < HM; r++) {
        float v0 = base[r * WM + lane];
        unsigned b0 = __ballot_sync(0xFFFFFFFFu, v0 < gamma);
        float v1 = (lane < WM - 32) ? base[r * WM + 32 + lane] : 1.0f;
        unsigned b1 = __ballot_sync(0xFFFFFFFFu, v1 < gamma);
        unsigned long long w = (unsigned long long)b0 |
                               ((unsigned long long)b1 << 32);
        // horizontal dilation: OR of shifts 0..6
        unsigned long long d = w | (w << 1);   // 0..1
        d |= d << 2;                            // 0..3
        d |= d << 3;                            // 0..6
        if (lane == 0) rows[warp][r] = d;
    }
    __syncwarp();

    int cnt = 0;
    for (int h = lane; h < HH; h += 32) {
        int r0 = h - 6; if (r0 < 0) r0 = 0;
        int r1 = h;     if (r1 > HM - 1) r1 = HM - 1;
        unsigned long long o = 0ULL;
        #pragma unroll 4
        for (int r = r0; r <= r1; r++) o |= rows[warp][r];
        g_blocked[(size_t)plane * HH + h] = o;
        cnt += __popcll(o);
    }
    #pragma unroll
    for (int off = 16; off; off >>= 1)
        cnt += __shfl_down_sync(0xFFFFFFFFu, cnt, off);
    if (lane == 0) atomicAdd(&g_count, (unsigned long long)cnt);
}

// Elementwise apply: out = x * (1-blocked) * scale, float4-vectorized.
// 56 cols per row = 14 float4s per row, rows never straddle a float4.
__global__ __launch_bounds__(256) void apply_kernel(const float4* __restrict__ x4,
                                                    float4* __restrict__ out4) {
    int v = blockIdx.x * blockDim.x + threadIdx.x;
    if (v >= NVEC) return;

    unsigned long long cnt = g_count;
    float s = (float)((double)NTOT / (double)(NTOT - (long long)cnt));

    int rowg = v / 14;               // global row index == plane*56 + row
    int c4   = v - rowg * 14;        // which float4 within row
    unsigned bits = (unsigned)(g_blocked[rowg] >> (c4 * 4)) & 0xFu;

    float4 xi = x4[v];
    float4 o;
    o.x = (bits & 1u) ? 0.0f : xi.x * s;
    o.y = (bits & 2u) ? 0.0f : xi.y * s;
    o.z = (bits & 4u) ? 0.0f : xi.z * s;
    o.w = (bits & 8u) ? 0.0f : xi.w * s;
    out4[v] = o;
}

extern "C" void kernel_launch(void* const* d_in, const int* in_sizes, int n_in,
                              void* d_out, int out_size) {
    const float* x      = (const float*)d_in[0];
    const float* mask_u = (const float*)d_in[1];
    float* out          = (float*)d_out;

    init_kernel<<<1, 1>>>();
    mask_kernel<<<NPLANES / 8, 256>>>(mask_u);
    apply_kernel<<<NVEC / 256, 256>>>((const float4*)x, (float4*)out);
}

// round 2
// speedup vs baseline: 1.0310x; 1.0310x over previous
#include <cuda_runtime.h>
#include <cstdint>

#define NPLANES 16384      // 64*256
#define HM 50
#define WM 50
#define HH 56
#define NTOT 51380224      // 64*256*56*56
#define NVEC (NTOT/4)      // 12845056 float4s
#define ROWWORDS (NPLANES*HH)
#define PPB 4              // planes per block (mask kernel)
#define PLANE_ELEMS (HM*WM)   // 2500 floats = 10000 B (16B-aligned stride)

typedef unsigned long long ull;

__device__ ull g_blocked[ROWWORDS];   // 7.34 MB: one 64-bit row mask per output row
__device__ ull g_count;

__global__ void init_kernel() { g_count = 0ULL; }

// 4 planes per block. Phase 1: coalesced float4 staging into smem (high MLP).
// Phase 2: 2 warps per plane do ballot+horizontal dilation from smem.
// Phase 3: 2 warps per plane do vertical OR over 7 rows, write g_blocked, count.
__global__ __launch_bounds__(256) void mask_kernel(const float* __restrict__ mask_u) {
    const float gamma = (float)(0.1 / 49.0 * 3136.0 / 2500.0);

    __shared__ float sm[PPB * PLANE_ELEMS];          // 40000 B
    __shared__ ull rows[PPB][HM];                    // 1600 B
    __shared__ int wsum[8];

    const int tid  = threadIdx.x;
    const int warp = tid >> 5;
    const int lane = tid & 31;

    // ---- Phase 1: stream 4 planes (2500 float4s) into shared, coalesced ----
    const float4* src = (const float4*)(mask_u + (size_t)blockIdx.x * (PPB * PLANE_ELEMS));
    float4* dst = (float4*)sm;
    #pragma unroll
    for (int i = 0; i < 10; i++) {
        int idx = tid + i * 256;
        if (idx < (PPB * PLANE_ELEMS) / 4) dst[idx] = src[idx];
    }
    __syncthreads();

    // ---- Phase 2: threshold + bitpack + horizontal 7-dilation (from smem) ----
    const int plane = warp >> 1;               // 0..3
    const float* p = sm + plane * PLANE_ELEMS;
    const int rbeg = (warp & 1) * 25;          // rows 0..24 or 25..49
    #pragma unroll 5
    for (int r = rbeg; r < rbeg + 25; r++) {
        float v0 = p[r * WM + lane];
        unsigned b0 = __ballot_sync(0xFFFFFFFFu, v0 < gamma);
        float v1 = (lane < WM - 32) ? p[r * WM + 32 + lane] : 1.0f;
        unsigned b1 = __ballot_sync(0xFFFFFFFFu, v1 < gamma);
        ull w = (ull)b0 | ((ull)b1 << 32);
        ull d = w | (w << 1);   // shifts 0..1
        d |= d << 2;            // 0..3
        d |= d << 3;            // 0..6
        if (lane == 0) rows[plane][r] = d;
    }
    __syncthreads();

    // ---- Phase 3: vertical OR over window [h-6, h], write + popcount ----
    int cnt = 0;
    const int h = (warp & 1) * 28 + lane;      // 0..27 or 28..55
    if (lane < 28) {
        int a = h - 6; if (a < 0) a = 0;
        int b = h;     if (b > HM - 1) b = HM - 1;
        ull o = 0ULL;
        #pragma unroll 4
        for (int r = a; r <= b; r++) o |= rows[plane][r];
        size_t gp = (size_t)blockIdx.x * PPB + plane;
        g_blocked[gp * HH + h] = o;
        cnt = __popcll(o);
    }
    #pragma unroll
    for (int off = 16; off; off >>= 1)
        cnt += __shfl_down_sync(0xFFFFFFFFu, cnt, off);
    if (lane == 0) wsum[warp] = cnt;
    __syncthreads();
    if (tid == 0) {
        int t = 0;
        #pragma unroll
        for (int w = 0; w < 8; w++) t += wsum[w];
        atomicAdd(&g_count, (ull)t);
    }
}

// Elementwise apply: out = x * (1-blocked) * scale, float4-vectorized.
// 56 cols/row = 14 float4s per row; rows never straddle a float4.
__global__ __launch_bounds__(256) void apply_kernel(const float4* __restrict__ x4,
                                                    float4* __restrict__ out4) {
    int v = blockIdx.x * blockDim.x + threadIdx.x;
    if (v >= NVEC) return;

    ull cnt = g_count;
    float s = (float)((double)NTOT / (double)(NTOT - (long long)cnt));

    int rowg = v / 14;               // global row index == plane*56 + row
    int c4   = v - rowg * 14;
    unsigned bits = (unsigned)(g_blocked[rowg] >> (c4 * 4)) & 0xFu;

    float4 xi = x4[v];
    float4 o;
    o.x = (bits & 1u) ? 0.0f : xi.x * s;
    o.y = (bits & 2u) ? 0.0f : xi.y * s;
    o.z = (bits & 4u) ? 0.0f : xi.z * s;
    o.w = (bits & 8u) ? 0.0f : xi.w * s;
    out4[v] = o;
}

extern "C" void kernel_launch(void* const* d_in, const int* in_sizes, int n_in,
                              void* d_out, int out_size) {
    const float* x      = (const float*)d_in[0];
    const float* mask_u = (const float*)d_in[1];
    float* out          = (float*)d_out;

    init_kernel<<<1, 1>>>();
    mask_kernel<<<NPLANES / PPB, 256>>>(mask_u);
    apply_kernel<<<NVEC / 256, 256>>>((const float4*)x, (float4*)out);
}

// round 3
// speedup vs baseline: 2.7210x; 2.6391x over previous
#include <cuda_runtime.h>
#include <cstdint>

#define NPLANES 16384      // 64*256
#define HM 50
#define WM 50
#define HH 56
#define NTOT 51380224      // 64*256*56*56
#define NVEC (NTOT/4)      // 12845056 float4s
#define NVEC2 (NVEC/2)     // 6422528 (divisible by 14*256? 6422528/14=458752 exact)
#define ROWWORDS (NPLANES*HH)
#define PPB 4              // planes per block (mask kernel)
#define PLANE_ELEMS (HM*WM)

typedef unsigned long long ull;

__device__ ull g_blocked[ROWWORDS];   // 7.34 MB: 64-bit row mask per output row
__device__ ull g_count = 0ULL;        // invariant: 0 at entry of every kernel_launch
__device__ float g_scale;

// 4 planes per block. Phase 1: coalesced float4 staging into smem.
// Phase 2: 2 warps/plane: threshold + bitpack + horizontal 7-dilation.
// Phase 3: vertical OR over 7 rows, write g_blocked, popcount + block atomic.
__global__ __launch_bounds__(256) void mask_kernel(const float* __restrict__ mask_u) {
    const float gamma = (float)(0.1 / 49.0 * 3136.0 / 2500.0);

    __shared__ float sm[PPB * PLANE_ELEMS];          // 40000 B
    __shared__ ull rows[PPB][HM];
    __shared__ int wsum[8];

    const int tid  = threadIdx.x;
    const int warp = tid >> 5;
    const int lane = tid & 31;

    const float4* src = (const float4*)(mask_u + (size_t)blockIdx.x * (PPB * PLANE_ELEMS));
    float4* dst = (float4*)sm;
    #pragma unroll
    for (int i = 0; i < 10; i++) {
        int idx = tid + i * 256;
        if (idx < (PPB * PLANE_ELEMS) / 4) dst[idx] = src[idx];
    }
    __syncthreads();

    const int plane = warp >> 1;
    const float* p = sm + plane * PLANE_ELEMS;
    const int rbeg = (warp & 1) * 25;
    #pragma unroll 5
    for (int r = rbeg; r < rbeg + 25; r++) {
        float v0 = p[r * WM + lane];
        unsigned b0 = __ballot_sync(0xFFFFFFFFu, v0 < gamma);
        float v1 = (lane < WM - 32) ? p[r * WM + 32 + lane] : 1.0f;
        unsigned b1 = __ballot_sync(0xFFFFFFFFu, v1 < gamma);
        ull w = (ull)b0 | ((ull)b1 << 32);
        ull d = w | (w << 1);
        d |= d << 2;
        d |= d << 3;
        if (lane == 0) rows[plane][r] = d;
    }
    __syncthreads();

    int cnt = 0;
    const int h = (warp & 1) * 28 + lane;
    if (lane < 28) {
        int a = h - 6; if (a < 0) a = 0;
        int b = h;     if (b > HM - 1) b = HM - 1;
        ull o = 0ULL;
        #pragma unroll 4
        for (int r = a; r <= b; r++) o |= rows[plane][r];
        size_t gp = (size_t)blockIdx.x * PPB + plane;
        g_blocked[gp * HH + h] = o;
        cnt = __popcll(o);
    }
    #pragma unroll
    for (int off = 16; off; off >>= 1)
        cnt += __shfl_down_sync(0xFFFFFFFFu, cnt, off);
    if (lane == 0) wsum[warp] = cnt;
    __syncthreads();
    if (tid == 0) {
        int t = 0;
        #pragma unroll
        for (int w = 0; w < 8; w++) t += wsum[w];
        atomicAdd(&g_count, (ull)t);
    }
}

// Compute scale once (exact double), then reset g_count for the next replay.
__global__ void scale_kernel() {
    ull cnt = g_count;
    g_scale = (float)((double)NTOT / (double)(NTOT - (long long)cnt));
    g_count = 0ULL;
}

// Elementwise apply: out = x * (1-blocked) * scale. 2 float4s per thread.
__global__ __launch_bounds__(256) void apply_kernel(const float4* __restrict__ x4,
                                                    float4* __restrict__ out4) {
    const int v0 = blockIdx.x * blockDim.x + threadIdx.x;
    const float s = g_scale;

    #pragma unroll
    for (int half = 0; half < 2; half++) {
        int v = v0 + half * NVEC2;
        int rowg = v / 14;
        int c4   = v - rowg * 14;
        unsigned bits = (unsigned)(g_blocked[rowg] >> (c4 * 4)) & 0xFu;

        float4 xi = __ldcs(&x4[v]);
        float4 o;
        o.x = (bits & 1u) ? 0.0f : xi.x * s;
        o.y = (bits & 2u) ? 0.0f : xi.y * s;
        o.z = (bits & 4u) ? 0.0f : xi.z * s;
        o.w = (bits & 8u) ? 0.0f : xi.w * s;
        __stcs(&out4[v], o);
    }
}

extern "C" void kernel_launch(void* const* d_in, const int* in_sizes, int n_in,
                              void* d_out, int out_size) {
    const float* x      = (const float*)d_in[0];
    const float* mask_u = (const float*)d_in[1];
    float* out          = (float*)d_out;

    mask_kernel<<<NPLANES / PPB, 256>>>(mask_u);
    scale_kernel<<<1, 1>>>();
    apply_kernel<<<NVEC2 / 256, 256>>>((const float4*)x, (float4*)out);
}

// round 4
// speedup vs baseline: 2.9042x; 1.0673x over previous
#include <cuda_runtime.h>
#include <cstdint>

#define NPLANES 16384      // 64*256
#define HM 50
#define WM 50
#define HH 56
#define NTOT 51380224      // 64*256*56*56
#define NVEC (NTOT/4)      // 12845056 float4s
#define NVEC2 (NVEC/2)
#define ROWWORDS (NPLANES*HH)
#define PLANE_ELEMS (HM*WM)   // 2500
#define MASK_BLOCKS (NPLANES/8)

typedef unsigned long long ull;

__device__ ull g_blocked[ROWWORDS];     // 7.34 MB: 64-bit dilated row mask per output row
__device__ ull g_count = 0ULL;          // invariant: 0 at entry of every launch
__device__ unsigned g_done = 0u;        // block-completion ticket, reset each launch
__device__ float g_scale;

// One warp per plane (8 planes / 256-thread block).
// Sparse path: gamma ~ 0.0026, so ~6.4 hits per 2500-elem plane. Each lane
// streams float4s, tests min-of-4 against gamma, and only on a hit does a
// smem atomicOr of (0x7F << col) -- horizontal 7-dilation fused into insert.
// Epilogue: vertical OR over [h-6, h], write g_blocked, popcount, reduce.
// Last-finishing block computes g_scale and resets counters (replay-safe).
__global__ __launch_bounds__(256) void mask_kernel(const float* __restrict__ mask_u) {
    const float gamma = (float)(0.1 / 49.0 * 3136.0 / 2500.0);

    __shared__ ull rows[8][HM];
    __shared__ int wsum[8];

    const int tid  = threadIdx.x;
    const int warp = tid >> 5;
    const int lane = tid & 31;
    const int plane = blockIdx.x * 8 + warp;

    #pragma unroll
    for (int r = lane; r < HM; r += 32) rows[warp][r] = 0ULL;
    __syncwarp();

    const float4* p = (const float4*)(mask_u + (size_t)plane * PLANE_ELEMS);
    for (int i = lane; i < PLANE_ELEMS / 4; i += 32) {   // 625 float4s
        float4 v = __ldcs(&p[i]);
        float m = fminf(fminf(v.x, v.y), fminf(v.z, v.w));
        if (m < gamma) {                                  // rare (~1% of iters)
            int base = i * 4;
            if (v.x < gamma) { int e = base;     atomicOr(&rows[warp][e / WM], 0x7FULL << (e % WM)); }
            if (v.y < gamma) { int e = base + 1; atomicOr(&rows[warp][e / WM], 0x7FULL << (e % WM)); }
            if (v.z < gamma) { int e = base + 2; atomicOr(&rows[warp][e / WM], 0x7FULL << (e % WM)); }
            if (v.w < gamma) { int e = base + 3; atomicOr(&rows[warp][e / WM], 0x7FULL << (e % WM)); }
        }
    }
    __syncwarp();

    // vertical OR over the 7-row window, write dilated mask, count bits
    int cnt = 0;
    for (int h = lane; h < HH; h += 32) {
        int a = h - 6; if (a < 0) a = 0;
        int b = h;     if (b > HM - 1) b = HM - 1;
        ull o = 0ULL;
        for (int r = a; r <= b; r++) o |= rows[warp][r];
        g_blocked[(size_t)plane * HH + h] = o;
        cnt += __popcll(o);
    }
    #pragma unroll
    for (int off = 16; off; off >>= 1)
        cnt += __shfl_down_sync(0xFFFFFFFFu, cnt, off);
    if (lane == 0) wsum[warp] = cnt;
    __syncthreads();

    if (tid == 0) {
        int t = 0;
        #pragma unroll
        for (int w = 0; w < 8; w++) t += wsum[w];
        atomicAdd(&g_count, (ull)t);
        __threadfence();
        unsigned ticket = atomicAdd(&g_done, 1u);
        if (ticket == MASK_BLOCKS - 1) {                  // last block: finalize
            ull c = atomicAdd(&g_count, 0ULL);
            g_scale = (float)((double)NTOT / (double)(NTOT - (long long)c));
            g_count = 0ULL;                               // reset for next replay
            g_done  = 0u;
        }
    }
}

// Elementwise apply: out = x * (1-blocked) * scale. 2 float4s per thread,
// streaming hints on the 410 MB of x/out traffic. Already at ~7.1 TB/s.
__global__ __launch_bounds__(256) void apply_kernel(const float4* __restrict__ x4,
                                                    float4* __restrict__ out4) {
    const int v0 = blockIdx.x * blockDim.x + threadIdx.x;
    const float s = g_scale;

    #pragma unroll
    for (int half = 0; half < 2; half++) {
        int v = v0 + half * NVEC2;
        int rowg = v / 14;               // global row == plane*56 + h
        int c4   = v - rowg * 14;
        unsigned bits = (unsigned)(g_blocked[rowg] >> (c4 * 4)) & 0xFu;

        float4 xi = __ldcs(&x4[v]);
        float4 o;
        o.x = (bits & 1u) ? 0.0f : xi.x * s;
        o.y = (bits & 2u) ? 0.0f : xi.y * s;
        o.z = (bits & 4u) ? 0.0f : xi.z * s;
        o.w = (bits & 8u) ? 0.0f : xi.w * s;
        __stcs(&out4[v], o);
    }
}

extern "C" void kernel_launch(void* const* d_in, const int* in_sizes, int n_in,
                              void* d_out, int out_size) {
    const float* x      = (const float*)d_in[0];
    const float* mask_u = (const float*)d_in[1];
    float* out          = (float*)d_out;

    mask_kernel<<<MASK_BLOCKS, 256>>>(mask_u);
    apply_kernel<<<NVEC2 / 256, 256>>>((const float4*)x, (float4*)out);
}